// round 10
// baseline (speedup 1.0000x reference)
#include <cuda_runtime.h>
#include <math.h>
#include <stdint.h>

#define TT 49
#define UNITS 256
#define QN 9
#define DIMF 256
#define BATCH 2048
#define G4 1024
#define RS (TT * UNITS)
#define PI_F 3.14159265358979f

#define S_CS 260                // c-state / s-tile row stride (floats), 16B-divisible
#define KT 32                   // 256 / 8 k-tiles
#define RECUR_SMEM (4 * 16 * S_CS * 4)   // cs_full, cs_hi, cs_lo, ss = 66.6 KB

// ---- static device scratch ----
__device__ float    g_U[(size_t)TT * UNITS * UNITS];    // [t][k][n]
__device__ float    g_Whx[(size_t)DIMF * G4];           // x-part weights, gate-interleaved cols [k][j*4+g]
__device__ uint4    g_Wb4[(size_t)UNITS * G4 / 4];      // c-part weights tf32, per-warp-contiguous frag order
__device__ float    g_Xp[(size_t)BATCH * TT * G4];      // [bt*1024 + j*4 + g]
__device__ float    g_S[(size_t)BATCH * TT * UNITS];    // [bt*256 + j]

__device__ __forceinline__ float sigf(float x) {
    return __fdividef(1.0f, 1.0f + __expf(-x));
}
__device__ __forceinline__ float tanh_fast(float x) {
    return __fdividef(2.0f, 1.0f + __expf(-2.0f * x)) - 1.0f;
}

__device__ __forceinline__ uint32_t f2tf(float x) {
    uint32_t r;
    asm("cvt.rna.tf32.f32 %0, %1;" : "=r"(r) : "f"(x));
    return r;
}

__device__ __forceinline__ void mma_tf32(float* c, const uint32_t* a, const uint32_t* b) {
    asm volatile(
        "mma.sync.aligned.m16n8k8.row.col.f32.tf32.tf32.f32 "
        "{%0,%1,%2,%3}, {%4,%5,%6,%7}, {%8,%9}, {%0,%1,%2,%3};\n"
        : "+f"(c[0]), "+f"(c[1]), "+f"(c[2]), "+f"(c[3])
        : "r"(a[0]), "r"(a[1]), "r"(a[2]), "r"(a[3]), "r"(b[0]), "r"(b[1]));
}

// ---------------------------------------------------------------------------
// U[t][k][n] = sum_q Q[k, n*9+q] * B[t][q]
// ---------------------------------------------------------------------------
__global__ void build_U(const float* __restrict__ Q) {
    int t = blockIdx.x, i = blockIdx.y, j = threadIdx.x;
    __shared__ float Bq[QN];
    if (threadIdx.x < QN) {
        int q = threadIdx.x;
        float tt = (float)t / (float)(TT - 1);
        float v;
        if (q == 0) v = 1.0f;
        else {
            int h = (q + 1) >> 1;
            float w = 2.0f * PI_F * (float)h * tt;
            v = 1.41421356237309515f * ((q & 1) ? sinf(w) : cosf(w));
        }
        Bq[q] = v;
    }
    __syncthreads();
    const float* qrow = Q + (size_t)i * (UNITS * QN) + (size_t)j * QN;
    float acc = 0.0f;
#pragma unroll
    for (int q = 0; q < QN; q++) acc = fmaf(qrow[q], Bq[q], acc);
    g_U[((size_t)t * UNITS + i) * UNITS + j] = acc;
}

// ---------------------------------------------------------------------------
// x-part weights -> gate-interleaved columns: Whx[k][j*4+g]
// ---------------------------------------------------------------------------
__global__ void prep_Whx(const float* __restrict__ Wf, const float* __restrict__ Wi,
                         const float* __restrict__ Wc, const float* __restrict__ Wo) {
    int idx = blockIdx.x * blockDim.x + threadIdx.x;
    if (idx >= 256 * UNITS) return;
    int k = idx >> 8, j = idx & 255;
    int src = (k + 256) * UNITS + j;       // x-part = rows 256..511 of cat weight
    float4 v = make_float4(Wf[src], Wi[src], Wc[src], Wo[src]);
    *(float4*)(g_Whx + (size_t)k * G4 + (size_t)j * 4) = v;
}

// ---------------------------------------------------------------------------
// c-part weights -> tf32 B-fragments, per-warp-contiguous layout:
// uint32 idx = (((kt*8 + w)*32 + lane)*16 + ni)*2 + e
//   n = (w*16+ni)*8 + (lane>>2); k = kt*8 + (lane&3) + 4e; j = n>>2; gate = n&3
// ---------------------------------------------------------------------------
__global__ void prep_Wb(const float* __restrict__ Wf, const float* __restrict__ Wi,
                        const float* __restrict__ Wc, const float* __restrict__ Wo) {
    int idx = blockIdx.x * blockDim.x + threadIdx.x;
    if (idx >= UNITS * G4) return;
    int e    = idx & 1;
    int ni   = (idx >> 1) & 15;
    int lane = (idx >> 5) & 31;
    int w    = (idx >> 10) & 7;
    int kt   = idx >> 13;
    int n = (w * 16 + ni) * 8 + (lane >> 2);
    int k = kt * 8 + (lane & 3) + 4 * e;
    int j = n >> 2, gate = n & 3;
    const float* W = (gate == 0) ? Wf : (gate == 1) ? Wi : (gate == 2) ? Wc : Wo;
    ((uint32_t*)g_Wb4)[idx] = f2tf(W[(size_t)k * UNITS + j]);   // c-part = rows 0..255
}

// ---------------------------------------------------------------------------
// tf32 MMA GEMM: Xp = X(100352 x 256) @ Whx(256 x 1024); contiguous stores
// ---------------------------------------------------------------------------
__global__ __launch_bounds__(256) void xproj_mma(const float* __restrict__ A) {
    __shared__ uint32_t As[128][36];
    __shared__ uint32_t Bs[32][136];
    int tid = threadIdx.x;
    int bm = blockIdx.x, bn = blockIdx.y;
    int w = tid >> 5, lane = tid & 31;
    int wm = (w & 3) * 32, wn = (w >> 2) * 64;
    int g = lane >> 2, tc = lane & 3;

    const float* Ab = A + (size_t)bm * 128 * DIMF;
    const float* Bb = g_Whx + (size_t)bn * 128;

    int ar0 = tid >> 3, ac = (tid & 7) * 4;
    int br0 = tid >> 5, bc = (tid & 31) * 4;

    float c[2][8][4];
#pragma unroll
    for (int mi = 0; mi < 2; mi++)
#pragma unroll
        for (int ni = 0; ni < 8; ni++)
#pragma unroll
            for (int q = 0; q < 4; q++) c[mi][ni][q] = 0.0f;

    float4 ar[4], br[4];
#pragma unroll
    for (int i = 0; i < 4; i++) {
        ar[i] = *(const float4*)(Ab + (size_t)(ar0 + 32 * i) * DIMF + ac);
        br[i] = *(const float4*)(Bb + (size_t)(br0 + 8 * i) * G4 + bc);
    }

    for (int s = 0; s < 8; s++) {
        __syncthreads();
#pragma unroll
        for (int i = 0; i < 4; i++) {
            uint32_t* pa = &As[ar0 + 32 * i][ac];
            pa[0] = f2tf(ar[i].x); pa[1] = f2tf(ar[i].y);
            pa[2] = f2tf(ar[i].z); pa[3] = f2tf(ar[i].w);
            uint32_t* pb = &Bs[br0 + 8 * i][bc];
            pb[0] = f2tf(br[i].x); pb[1] = f2tf(br[i].y);
            pb[2] = f2tf(br[i].z); pb[3] = f2tf(br[i].w);
        }
        __syncthreads();
        if (s < 7) {
            int k0 = (s + 1) * 32;
#pragma unroll
            for (int i = 0; i < 4; i++) {
                ar[i] = *(const float4*)(Ab + (size_t)(ar0 + 32 * i) * DIMF + k0 + ac);
                br[i] = *(const float4*)(Bb + (size_t)(k0 + br0 + 8 * i) * G4 + bc);
            }
        }
#pragma unroll
        for (int kk = 0; kk < 4; kk++) {
            int k8 = kk * 8;
            uint32_t af[2][4];
#pragma unroll
            for (int mi = 0; mi < 2; mi++) {
                int r0 = wm + mi * 16 + g;
                af[mi][0] = As[r0][k8 + tc];
                af[mi][1] = As[r0 + 8][k8 + tc];
                af[mi][2] = As[r0][k8 + tc + 4];
                af[mi][3] = As[r0 + 8][k8 + tc + 4];
            }
            uint32_t bf[8][2];
#pragma unroll
            for (int ni = 0; ni < 8; ni++) {
                int nc = wn + ni * 8 + g;
                bf[ni][0] = Bs[k8 + tc][nc];
                bf[ni][1] = Bs[k8 + tc + 4][nc];
            }
#pragma unroll
            for (int mi = 0; mi < 2; mi++)
#pragma unroll
                for (int ni = 0; ni < 8; ni++)
                    mma_tf32(c[mi][ni], af[mi], bf[ni]);
        }
    }

    // contiguous coalesced stores (columns already gate-interleaved via Whx perm)
#pragma unroll
    for (int mi = 0; mi < 2; mi++) {
#pragma unroll
        for (int ni = 0; ni < 8; ni++) {
            int row0 = bm * 128 + wm + mi * 16 + g;
            int n0 = bn * 128 + wn + ni * 8 + 2 * tc;
            *(float2*)(g_Xp + (size_t)row0 * G4 + n0) =
                make_float2(c[mi][ni][0], c[mi][ni][1]);
            *(float2*)(g_Xp + (size_t)(row0 + 8) * G4 + n0) =
                make_float2(c[mi][ni][2], c[mi][ni][3]);
        }
    }
}

// ---------------------------------------------------------------------------
// Tensor-core recurrence. 128 blocks x 16 batch rows, 8 warps.
// MMA (c hi/lo tf32) -> shuffle epilogue (no gate smem round-trip)
// -> coalesced g_S store via small s-tile.
// ---------------------------------------------------------------------------
__global__ __launch_bounds__(256) void recur_mma() {
    extern __shared__ float sm[];
    float*    cs_full = sm;                                // [16][S_CS]
    uint32_t* cs_hi   = (uint32_t*)(cs_full + 16 * S_CS);  // [16][S_CS]
    uint32_t* cs_lo   = cs_hi + 16 * S_CS;                 // [16][S_CS]
    float*    ss      = (float*)(cs_lo + 16 * S_CS);       // [16][S_CS]

    int tid = threadIdx.x;
    int w = tid >> 5, lane = tid & 31;
    int g = lane >> 2;
    int tc = lane & 3;
    int b0 = blockIdx.x * 16;
    bool even = !(lane & 1);
    int p_mine = even ? g : (g + 8);
    int jbase = w * 32 + ((lane >> 1) & 1);

    int sp = tid >> 4;
    int sc = (tid & 15) * 16;

    // precomputed smem fragment offsets (uniform across kt except +k8)
    int offA0 = g * S_CS + tc;
    int offA1 = (g + 8) * S_CS + tc;

#pragma unroll
    for (int p = 0; p < 16; p++) {
        cs_full[p * S_CS + tid] = 0.0f;
        cs_hi[p * S_CS + tid] = 0u;
        cs_lo[p * S_CS + tid] = 0u;
    }
    __syncthreads();

    const float4* __restrict__ Xp4 = (const float4*)g_Xp;

    for (int t = 0; t < TT; t++) {
        float acc[16][4];
#pragma unroll
        for (int ni = 0; ni < 16; ni++)
#pragma unroll
            for (int q = 0; q < 4; q++) acc[ni][q] = 0.0f;

#pragma unroll 2
        for (int kt = 0; kt < KT; kt++) {
            int k8 = kt * 8;
            size_t base = ((size_t)(kt * 8 + w) * 32 + lane) * 8;
            // front-batch the 8 weight LDG.128s so their latency overlaps the LDS below
            uint4 q[8];
#pragma unroll
            for (int i = 0; i < 8; i++) q[i] = g_Wb4[base + i];

            uint32_t ah[4], al[4];
            ah[0] = cs_hi[offA0 + k8];
            ah[1] = cs_hi[offA1 + k8];
            ah[2] = cs_hi[offA0 + k8 + 4];
            ah[3] = cs_hi[offA1 + k8 + 4];
            al[0] = cs_lo[offA0 + k8];
            al[1] = cs_lo[offA1 + k8];
            al[2] = cs_lo[offA0 + k8 + 4];
            al[3] = cs_lo[offA1 + k8 + 4];
#pragma unroll
            for (int i = 0; i < 8; i++) {
                uint32_t b0f[2] = {q[i].x, q[i].y};
                uint32_t b1f[2] = {q[i].z, q[i].w};
                mma_tf32(acc[2 * i], ah, b0f);
                mma_tf32(acc[2 * i], al, b0f);
                mma_tf32(acc[2 * i + 1], ah, b1f);
                mma_tf32(acc[2 * i + 1], al, b1f);
            }
        }

        // shuffle epilogue: lane^1 pairs exchange gate halves
#pragma unroll
        for (int ni = 0; ni < 16; ni++) {
            float c0 = acc[ni][0], c1 = acc[ni][1], c2 = acc[ni][2], c3 = acc[ni][3];
            float r0 = __shfl_xor_sync(0xffffffffu, c0, 1);
            float r1 = __shfl_xor_sync(0xffffffffu, c1, 1);
            float r2 = __shfl_xor_sync(0xffffffffu, c2, 1);
            float r3 = __shfl_xor_sync(0xffffffffu, c3, 1);
            float gf = even ? c0 : r2;
            float gi = even ? c1 : r3;
            float gc = even ? r0 : c2;
            float go = even ? r1 : c3;
            int j = jbase + 2 * ni;

            float4 xv = Xp4[((size_t)(b0 + p_mine) * TT + t) * UNITS + j];
            float f  = sigf(gf + xv.x);
            float i_ = sigf(gi + xv.y);
            float gg = sigf(gc + xv.z);
            float oo = tanh_fast(go + xv.w);
            float cold = cs_full[p_mine * S_CS + j];
            float cnew = fmaf(f, cold, i_ * gg);
            cs_full[p_mine * S_CS + j] = cnew;
            uint32_t hi = f2tf(cnew);
            cs_hi[p_mine * S_CS + j] = hi;
            cs_lo[p_mine * S_CS + j] = f2tf(cnew - __uint_as_float(hi));
            ss[p_mine * S_CS + j] = oo * tanh_fast(cnew);
        }
        __syncthreads();

        // coalesced g_S store from s-tile
        {
            size_t gb = ((size_t)(b0 + sp) * TT + t) * UNITS + sc;
#pragma unroll
            for (int i = 0; i < 4; i++) {
                float4 v = *(const float4*)&ss[sp * S_CS + sc + i * 4];
                *(float4*)&g_S[gb + i * 4] = v;
            }
        }
        __syncthreads();
    }
}

// ---------------------------------------------------------------------------
// tf32 MMA: out[b,t,:] = tanh(S[b,t,:] @ U[t]); grid (16, 2, 49)
// ---------------------------------------------------------------------------
__global__ __launch_bounds__(256) void hproj_mma(float* __restrict__ out) {
    __shared__ uint32_t As[128][36];
    __shared__ uint32_t Bs[32][136];
    int tid = threadIdx.x;
    int bm = blockIdx.x, bn = blockIdx.y, t = blockIdx.z;
    int w = tid >> 5, lane = tid & 31;
    int wm = (w & 3) * 32, wn = (w >> 2) * 64;
    int g = lane >> 2, tc = lane & 3;

    const float* Ab = g_S + (size_t)bm * 128 * RS + (size_t)t * UNITS;
    const float* Bb = g_U + (size_t)t * UNITS * UNITS + (size_t)bn * 128;

    int ar0 = tid >> 3, ac = (tid & 7) * 4;
    int br0 = tid >> 5, bc = (tid & 31) * 4;

    float c[2][8][4];
#pragma unroll
    for (int mi = 0; mi < 2; mi++)
#pragma unroll
        for (int ni = 0; ni < 8; ni++)
#pragma unroll
            for (int q = 0; q < 4; q++) c[mi][ni][q] = 0.0f;

    float4 ar[4], br[4];
#pragma unroll
    for (int i = 0; i < 4; i++) {
        ar[i] = *(const float4*)(Ab + (size_t)(ar0 + 32 * i) * RS + ac);
        br[i] = *(const float4*)(Bb + (size_t)(br0 + 8 * i) * UNITS + bc);
    }

    for (int s = 0; s < 8; s++) {
        __syncthreads();
#pragma unroll
        for (int i = 0; i < 4; i++) {
            uint32_t* pa = &As[ar0 + 32 * i][ac];
            pa[0] = f2tf(ar[i].x); pa[1] = f2tf(ar[i].y);
            pa[2] = f2tf(ar[i].z); pa[3] = f2tf(ar[i].w);
            uint32_t* pb = &Bs[br0 + 8 * i][bc];
            pb[0] = f2tf(br[i].x); pb[1] = f2tf(br[i].y);
            pb[2] = f2tf(br[i].z); pb[3] = f2tf(br[i].w);
        }
        __syncthreads();
        if (s < 7) {
            int k0 = (s + 1) * 32;
#pragma unroll
            for (int i = 0; i < 4; i++) {
                ar[i] = *(const float4*)(Ab + (size_t)(ar0 + 32 * i) * RS + k0 + ac);
                br[i] = *(const float4*)(Bb + (size_t)(k0 + br0 + 8 * i) * UNITS + bc);
            }
        }
#pragma unroll
        for (int kk = 0; kk < 4; kk++) {
            int k8 = kk * 8;
            uint32_t af[2][4];
#pragma unroll
            for (int mi = 0; mi < 2; mi++) {
                int r0 = wm + mi * 16 + g;
                af[mi][0] = As[r0][k8 + tc];
                af[mi][1] = As[r0 + 8][k8 + tc];
                af[mi][2] = As[r0][k8 + tc + 4];
                af[mi][3] = As[r0 + 8][k8 + tc + 4];
            }
            uint32_t bf[8][2];
#pragma unroll
            for (int ni = 0; ni < 8; ni++) {
                int nc = wn + ni * 8 + g;
                bf[ni][0] = Bs[k8 + tc][nc];
                bf[ni][1] = Bs[k8 + tc + 4][nc];
            }
#pragma unroll
            for (int mi = 0; mi < 2; mi++)
#pragma unroll
                for (int ni = 0; ni < 8; ni++)
                    mma_tf32(c[mi][ni], af[mi], bf[ni]);
        }
    }

    float* Cb = out + (size_t)bm * 128 * RS + (size_t)t * UNITS + (size_t)bn * 128;
#pragma unroll
    for (int mi = 0; mi < 2; mi++) {
#pragma unroll
        for (int ni = 0; ni < 8; ni++) {
            int r0 = wm + mi * 16 + g;
            int col = wn + ni * 8 + 2 * tc;
            float2 v0 = make_float2(tanhf(c[mi][ni][0]), tanhf(c[mi][ni][1]));
            float2 v1 = make_float2(tanhf(c[mi][ni][2]), tanhf(c[mi][ni][3]));
            *(float2*)(Cb + (size_t)r0 * RS + col) = v0;
            *(float2*)(Cb + (size_t)(r0 + 8) * RS + col) = v1;
        }
    }
}

extern "C" void kernel_launch(void* const* d_in, const int* in_sizes, int n_in,
                              void* d_out, int out_size) {
    const float* x  = (const float*)d_in[0];
    const float* Wf = (const float*)d_in[1];
    const float* Wi = (const float*)d_in[2];
    const float* Wc = (const float*)d_in[3];
    const float* Wo = (const float*)d_in[4];
    const float* Q  = (const float*)d_in[5];
    float* out = (float*)d_out;

    cudaFuncSetAttribute(recur_mma, cudaFuncAttributeMaxDynamicSharedMemorySize, RECUR_SMEM);

    build_U<<<dim3(TT, UNITS), 256>>>(Q);
    prep_Whx<<<(256 * UNITS + 255) / 256, 256>>>(Wf, Wi, Wc, Wo);
    prep_Wb<<<(UNITS * G4 + 255) / 256, 256>>>(Wf, Wi, Wc, Wo);
    xproj_mma<<<dim3(BATCH * TT / 128, G4 / 128), 256>>>(x);
    recur_mma<<<BATCH / 16, 256, RECUR_SMEM>>>();
    hproj_mma<<<dim3(BATCH / 128, UNITS / 128, TT), 256>>>(out);
}

// round 12
// speedup vs baseline: 1.1337x; 1.1337x over previous
#include <cuda_runtime.h>
#include <math.h>
#include <stdint.h>

#define TT 49
#define UNITS 256
#define QN 9
#define DIMF 256
#define BATCH 2048
#define G4 1024
#define RS (TT * UNITS)
#define PI_F 3.14159265358979f

#define S_GS 1032               // gate tile row stride (floats)
#define S_CS 260                // c-state row stride (floats)
#define KT 32                   // 256 / 8 k-tiles
#define RECUR_SMEM ((16 * S_GS + 2 * 16 * S_CS) * 4)   // gs + cs_full + cs_hi = 97 KB

// ---- static device scratch ----
__device__ float    g_U[(size_t)TT * UNITS * UNITS];   // [t][k][n]
__device__ float    g_Whx[(size_t)DIMF * G4];          // x-part weights, gate-interleaved cols [k][j*4+g]
__device__ uint32_t g_Wb[(size_t)UNITS * G4];          // c-part weights, tf32, MMA-fragment order
__device__ float    g_Xp[(size_t)BATCH * TT * G4];     // gate-interleaved [bt*1024 + j*4 + g]
__device__ float    g_S[(size_t)BATCH * TT * UNITS];   // [bt*256 + j]

__device__ __forceinline__ float sigf(float x) {
    return __fdividef(1.0f, 1.0f + __expf(-x));
}
__device__ __forceinline__ float tanh_fast(float x) {
    return __fdividef(2.0f, 1.0f + __expf(-2.0f * x)) - 1.0f;
}

__device__ __forceinline__ uint32_t f2tf(float x) {
    uint32_t r;
    asm("cvt.rna.tf32.f32 %0, %1;" : "=r"(r) : "f"(x));
    return r;
}

__device__ __forceinline__ void mma_tf32(float* c, const uint32_t* a, const uint32_t* b) {
    asm volatile(
        "mma.sync.aligned.m16n8k8.row.col.f32.tf32.tf32.f32 "
        "{%0,%1,%2,%3}, {%4,%5,%6,%7}, {%8,%9}, {%0,%1,%2,%3};\n"
        : "+f"(c[0]), "+f"(c[1]), "+f"(c[2]), "+f"(c[3])
        : "r"(a[0]), "r"(a[1]), "r"(a[2]), "r"(a[3]), "r"(b[0]), "r"(b[1]));
}

// ---------------------------------------------------------------------------
// U[t][k][n] = sum_q Q[k, n*9+q] * B[t][q]
// ---------------------------------------------------------------------------
__global__ void build_U(const float* __restrict__ Q) {
    int t = blockIdx.x, i = blockIdx.y, j = threadIdx.x;
    __shared__ float Bq[QN];
    if (threadIdx.x < QN) {
        int q = threadIdx.x;
        float tt = (float)t / (float)(TT - 1);
        float v;
        if (q == 0) v = 1.0f;
        else {
            int h = (q + 1) >> 1;
            float w = 2.0f * PI_F * (float)h * tt;
            v = 1.41421356237309515f * ((q & 1) ? sinf(w) : cosf(w));
        }
        Bq[q] = v;
    }
    __syncthreads();
    const float* qrow = Q + (size_t)i * (UNITS * QN) + (size_t)j * QN;
    float acc = 0.0f;
#pragma unroll
    for (int q = 0; q < QN; q++) acc = fmaf(qrow[q], Bq[q], acc);
    g_U[((size_t)t * UNITS + i) * UNITS + j] = acc;
}

// ---------------------------------------------------------------------------
// x-part weights -> gate-interleaved columns: Whx[k][j*4+g]
// ---------------------------------------------------------------------------
__global__ void prep_Whx(const float* __restrict__ Wf, const float* __restrict__ Wi,
                         const float* __restrict__ Wc, const float* __restrict__ Wo) {
    int idx = blockIdx.x * blockDim.x + threadIdx.x;
    if (idx >= 256 * UNITS) return;
    int k = idx >> 8, j = idx & 255;
    int src = (k + 256) * UNITS + j;       // x-part = rows 256..511 of cat weight
    float4 v = make_float4(Wf[src], Wi[src], Wc[src], Wo[src]);
    *(float4*)(g_Whx + (size_t)k * G4 + (size_t)j * 4) = v;
}

// ---------------------------------------------------------------------------
// c-part weights -> tf32, m16n8k8 B-fragment order (round-4 measured layout):
// out idx = ((kt*128 + nt)*64 + lane*2 + e)
//   k = kt*8 + (lane&3) + 4e ; n = nt*8 + (lane>>2) ; j = n>>2 ; gate = n&3
// ---------------------------------------------------------------------------
__global__ void prep_Wb(const float* __restrict__ Wf, const float* __restrict__ Wi,
                        const float* __restrict__ Wc, const float* __restrict__ Wo) {
    int idx = blockIdx.x * blockDim.x + threadIdx.x;
    if (idx >= UNITS * G4) return;
    int e = idx & 1;
    int lane = (idx >> 1) & 31;
    int nt = (idx >> 6) & 127;
    int kt = idx >> 13;
    int k = kt * 8 + (lane & 3) + 4 * e;
    int n = nt * 8 + (lane >> 2);
    int j = n >> 2, gate = n & 3;
    const float* W = (gate == 0) ? Wf : (gate == 1) ? Wi : (gate == 2) ? Wc : Wo;
    g_Wb[idx] = f2tf(W[(size_t)k * UNITS + j]);   // c-part = rows 0..255
}

// ---------------------------------------------------------------------------
// tf32 MMA GEMM: Xp = X(100352 x 256) @ Whx(256 x 1024); contiguous stores
// (measured 348us in round 10 — keep)
// ---------------------------------------------------------------------------
__global__ __launch_bounds__(256) void xproj_mma(const float* __restrict__ A) {
    __shared__ uint32_t As[128][36];
    __shared__ uint32_t Bs[32][136];
    int tid = threadIdx.x;
    int bm = blockIdx.x, bn = blockIdx.y;
    int w = tid >> 5, lane = tid & 31;
    int wm = (w & 3) * 32, wn = (w >> 2) * 64;
    int g = lane >> 2, tc = lane & 3;

    const float* Ab = A + (size_t)bm * 128 * DIMF;
    const float* Bb = g_Whx + (size_t)bn * 128;

    int ar0 = tid >> 3, ac = (tid & 7) * 4;
    int br0 = tid >> 5, bc = (tid & 31) * 4;

    float c[2][8][4];
#pragma unroll
    for (int mi = 0; mi < 2; mi++)
#pragma unroll
        for (int ni = 0; ni < 8; ni++)
#pragma unroll
            for (int q = 0; q < 4; q++) c[mi][ni][q] = 0.0f;

    float4 ar[4], br[4];
#pragma unroll
    for (int i = 0; i < 4; i++) {
        ar[i] = *(const float4*)(Ab + (size_t)(ar0 + 32 * i) * DIMF + ac);
        br[i] = *(const float4*)(Bb + (size_t)(br0 + 8 * i) * G4 + bc);
    }

    for (int s = 0; s < 8; s++) {
        __syncthreads();
#pragma unroll
        for (int i = 0; i < 4; i++) {
            uint32_t* pa = &As[ar0 + 32 * i][ac];
            pa[0] = f2tf(ar[i].x); pa[1] = f2tf(ar[i].y);
            pa[2] = f2tf(ar[i].z); pa[3] = f2tf(ar[i].w);
            uint32_t* pb = &Bs[br0 + 8 * i][bc];
            pb[0] = f2tf(br[i].x); pb[1] = f2tf(br[i].y);
            pb[2] = f2tf(br[i].z); pb[3] = f2tf(br[i].w);
        }
        __syncthreads();
        if (s < 7) {
            int k0 = (s + 1) * 32;
#pragma unroll
            for (int i = 0; i < 4; i++) {
                ar[i] = *(const float4*)(Ab + (size_t)(ar0 + 32 * i) * DIMF + k0 + ac);
                br[i] = *(const float4*)(Bb + (size_t)(k0 + br0 + 8 * i) * G4 + bc);
            }
        }
#pragma unroll
        for (int kk = 0; kk < 4; kk++) {
            int k8 = kk * 8;
            uint32_t af[2][4];
#pragma unroll
            for (int mi = 0; mi < 2; mi++) {
                int r0 = wm + mi * 16 + g;
                af[mi][0] = As[r0][k8 + tc];
                af[mi][1] = As[r0 + 8][k8 + tc];
                af[mi][2] = As[r0][k8 + tc + 4];
                af[mi][3] = As[r0 + 8][k8 + tc + 4];
            }
            uint32_t bf[8][2];
#pragma unroll
            for (int ni = 0; ni < 8; ni++) {
                int nc = wn + ni * 8 + g;
                bf[ni][0] = Bs[k8 + tc][nc];
                bf[ni][1] = Bs[k8 + tc + 4][nc];
            }
#pragma unroll
            for (int mi = 0; mi < 2; mi++)
#pragma unroll
                for (int ni = 0; ni < 8; ni++)
                    mma_tf32(c[mi][ni], af[mi], bf[ni]);
        }
    }

#pragma unroll
    for (int mi = 0; mi < 2; mi++) {
#pragma unroll
        for (int ni = 0; ni < 8; ni++) {
            int row0 = bm * 128 + wm + mi * 16 + g;
            int n0 = bn * 128 + wn + ni * 8 + 2 * tc;
            *(float2*)(g_Xp + (size_t)row0 * G4 + n0) =
                make_float2(c[mi][ni][0], c[mi][ni][1]);
            *(float2*)(g_Xp + (size_t)(row0 + 8) * G4 + n0) =
                make_float2(c[mi][ni][2], c[mi][ni][3]);
        }
    }
}

// ---------------------------------------------------------------------------
// Tensor-core recurrence (round-4 measured structure, single c_hi MMA).
// 128 blocks x 16 batch rows, 8 warps. Per t:
//   G(16x1024) = c_hi(tf32) @ Wb(tf32), smem gate staging, coalesced epilogue.
// ---------------------------------------------------------------------------
__global__ __launch_bounds__(256) void recur_mma() {
    extern __shared__ float sm[];
    float*    gs      = sm;                               // [16][S_GS]
    float*    cs_full = sm + 16 * S_GS;                   // [16][S_CS]
    uint32_t* cs_hi   = (uint32_t*)(cs_full + 16 * S_CS); // [16][S_CS]

    int tid = threadIdx.x;
    int w = tid >> 5, lane = tid & 31;
    int g = lane >> 2, tc = lane & 3;
    int b0 = blockIdx.x * 16;

#pragma unroll
    for (int p = 0; p < 16; p++) {
        cs_full[p * S_CS + tid] = 0.0f;
        cs_hi[p * S_CS + tid] = 0u;
    }
    __syncthreads();

    const uint2* __restrict__ Wb = (const uint2*)g_Wb;
    const float4* __restrict__ Xp4 = (const float4*)g_Xp;

    for (int t = 0; t < TT; t++) {
        float acc[16][4];
#pragma unroll
        for (int ni = 0; ni < 16; ni++)
#pragma unroll
            for (int q = 0; q < 4; q++) acc[ni][q] = 0.0f;

#pragma unroll 2
        for (int kt = 0; kt < KT; kt++) {
            int k8 = kt * 8;
            uint2 bf[16];
#pragma unroll
            for (int ni = 0; ni < 16; ni++)
                bf[ni] = Wb[(size_t)((kt * 128) + w * 16 + ni) * 32 + lane];
            uint32_t ah[4];
            ah[0] = cs_hi[g * S_CS + k8 + tc];
            ah[1] = cs_hi[(g + 8) * S_CS + k8 + tc];
            ah[2] = cs_hi[g * S_CS + k8 + tc + 4];
            ah[3] = cs_hi[(g + 8) * S_CS + k8 + tc + 4];
#pragma unroll
            for (int ni = 0; ni < 16; ni++)
                mma_tf32(acc[ni], ah, (const uint32_t*)&bf[ni]);
        }

        // stage gate tile to smem (n ordering = j*4 + gate)
#pragma unroll
        for (int ni = 0; ni < 16; ni++) {
            int n0 = w * 128 + ni * 8 + 2 * tc;
            *(float2*)&gs[g * S_GS + n0]       = make_float2(acc[ni][0], acc[ni][1]);
            *(float2*)&gs[(g + 8) * S_GS + n0] = make_float2(acc[ni][2], acc[ni][3]);
        }
        __syncthreads();

#pragma unroll 4
        for (int p = 0; p < 16; p++) {
            float4 gv = *(const float4*)&gs[p * S_GS + 4 * tid];
            float4 xv = Xp4[((size_t)(b0 + p) * TT + t) * UNITS + tid];
            float f  = sigf(gv.x + xv.x);
            float i_ = sigf(gv.y + xv.y);
            float gg = sigf(gv.z + xv.z);
            float oo = tanh_fast(gv.w + xv.w);
            float cold = cs_full[p * S_CS + tid];
            float cnew = fmaf(f, cold, i_ * gg);
            cs_full[p * S_CS + tid] = cnew;
            cs_hi[p * S_CS + tid] = f2tf(cnew);
            g_S[((size_t)(b0 + p) * TT + t) * UNITS + tid] = oo * tanh_fast(cnew);
        }
        __syncthreads();
    }
}

// ---------------------------------------------------------------------------
// tf32 MMA: out[b,t,:] = tanh(S[b,t,:] @ U[t]); grid (16, 2, 49)
// ---------------------------------------------------------------------------
__global__ __launch_bounds__(256) void hproj_mma(float* __restrict__ out) {
    __shared__ uint32_t As[128][36];
    __shared__ uint32_t Bs[32][136];
    int tid = threadIdx.x;
    int bm = blockIdx.x, bn = blockIdx.y, t = blockIdx.z;
    int w = tid >> 5, lane = tid & 31;
    int wm = (w & 3) * 32, wn = (w >> 2) * 64;
    int g = lane >> 2, tc = lane & 3;

    const float* Ab = g_S + (size_t)bm * 128 * RS + (size_t)t * UNITS;
    const float* Bb = g_U + (size_t)t * UNITS * UNITS + (size_t)bn * 128;

    int ar0 = tid >> 3, ac = (tid & 7) * 4;
    int br0 = tid >> 5, bc = (tid & 31) * 4;

    float c[2][8][4];
#pragma unroll
    for (int mi = 0; mi < 2; mi++)
#pragma unroll
        for (int ni = 0; ni < 8; ni++)
#pragma unroll
            for (int q = 0; q < 4; q++) c[mi][ni][q] = 0.0f;

    float4 ar[4], br[4];
#pragma unroll
    for (int i = 0; i < 4; i++) {
        ar[i] = *(const float4*)(Ab + (size_t)(ar0 + 32 * i) * RS + ac);
        br[i] = *(const float4*)(Bb + (size_t)(br0 + 8 * i) * UNITS + bc);
    }

    for (int s = 0; s < 8; s++) {
        __syncthreads();
#pragma unroll
        for (int i = 0; i < 4; i++) {
            uint32_t* pa = &As[ar0 + 32 * i][ac];
            pa[0] = f2tf(ar[i].x); pa[1] = f2tf(ar[i].y);
            pa[2] = f2tf(ar[i].z); pa[3] = f2tf(ar[i].w);
            uint32_t* pb = &Bs[br0 + 8 * i][bc];
            pb[0] = f2tf(br[i].x); pb[1] = f2tf(br[i].y);
            pb[2] = f2tf(br[i].z); pb[3] = f2tf(br[i].w);
        }
        __syncthreads();
        if (s < 7) {
            int k0 = (s + 1) * 32;
#pragma unroll
            for (int i = 0; i < 4; i++) {
                ar[i] = *(const float4*)(Ab + (size_t)(ar0 + 32 * i) * RS + k0 + ac);
                br[i] = *(const float4*)(Bb + (size_t)(k0 + br0 + 8 * i) * UNITS + bc);
            }
        }
#pragma unroll
        for (int kk = 0; kk < 4; kk++) {
            int k8 = kk * 8;
            uint32_t af[2][4];
#pragma unroll
            for (int mi = 0; mi < 2; mi++) {
                int r0 = wm + mi * 16 + g;
                af[mi][0] = As[r0][k8 + tc];
                af[mi][1] = As[r0 + 8][k8 + tc];
                af[mi][2] = As[r0][k8 + tc + 4];
                af[mi][3] = As[r0 + 8][k8 + tc + 4];
            }
            uint32_t bf[8][2];
#pragma unroll
            for (int ni = 0; ni < 8; ni++) {
                int nc = wn + ni * 8 + g;
                bf[ni][0] = Bs[k8 + tc][nc];
                bf[ni][1] = Bs[k8 + tc + 4][nc];
            }
#pragma unroll
            for (int mi = 0; mi < 2; mi++)
#pragma unroll
                for (int ni = 0; ni < 8; ni++)
                    mma_tf32(c[mi][ni], af[mi], bf[ni]);
        }
    }

    float* Cb = out + (size_t)bm * 128 * RS + (size_t)t * UNITS + (size_t)bn * 128;
#pragma unroll
    for (int mi = 0; mi < 2; mi++) {
#pragma unroll
        for (int ni = 0; ni < 8; ni++) {
            int r0 = wm + mi * 16 + g;
            int col = wn + ni * 8 + 2 * tc;
            float2 v0 = make_float2(tanhf(c[mi][ni][0]), tanhf(c[mi][ni][1]));
            float2 v1 = make_float2(tanhf(c[mi][ni][2]), tanhf(c[mi][ni][3]));
            *(float2*)(Cb + (size_t)r0 * RS + col) = v0;
            *(float2*)(Cb + (size_t)(r0 + 8) * RS + col) = v1;
        }
    }
}

extern "C" void kernel_launch(void* const* d_in, const int* in_sizes, int n_in,
                              void* d_out, int out_size) {
    const float* x  = (const float*)d_in[0];
    const float* Wf = (const float*)d_in[1];
    const float* Wi = (const float*)d_in[2];
    const float* Wc = (const float*)d_in[3];
    const float* Wo = (const float*)d_in[4];
    const float* Q  = (const float*)d_in[5];
    float* out = (float*)d_out;

    cudaFuncSetAttribute(recur_mma, cudaFuncAttributeMaxDynamicSharedMemorySize, RECUR_SMEM);

    build_U<<<dim3(TT, UNITS), 256>>>(Q);
    prep_Whx<<<(256 * UNITS + 255) / 256, 256>>>(Wf, Wi, Wc, Wo);
    prep_Wb<<<(UNITS * G4 + 255) / 256, 256>>>(Wf, Wi, Wc, Wo);
    xproj_mma<<<dim3(BATCH * TT / 128, G4 / 128), 256>>>(x);
    recur_mma<<<BATCH / 16, 256, RECUR_SMEM>>>();
    hproj_mma<<<dim3(BATCH / 128, UNITS / 128, TT), 256>>>(out);
}

// round 13
// speedup vs baseline: 1.5189x; 1.3397x over previous
#include <cuda_runtime.h>
#include <cuda_fp16.h>
#include <math.h>
#include <stdint.h>

#define TT 49
#define UNITS 256
#define QN 9
#define DIMF 256
#define BATCH 2048
#define G4 1024
#define RS (TT * UNITS)
#define PI_F 3.14159265358979f

#define S_GS 1032               // gate tile row stride (floats)
#define S_CS 260                // c-state fp32 row stride (floats)
#define S_CH 264                // c-state fp16 row stride (halves)
#define KT16 16                 // 256 / 16 k-tiles (fp16 MMA)
// gs + cs_full (floats) + cs_h (halves)
#define RECUR_SMEM ((16 * S_GS + 16 * S_CS) * 4 + 16 * S_CH * 2)

// ---- static device scratch ----
__device__ float    g_U[(size_t)TT * UNITS * UNITS];   // [t][k][n]
__device__ float    g_Whx[(size_t)DIMF * G4];          // x-part weights, gate-interleaved cols [k][j*4+g]
__device__ uint2    g_Wbh[(size_t)KT16 * 128 * 32];    // c-part weights fp16, m16n8k16 B-fragment order
__device__ float    g_Xp[(size_t)BATCH * TT * G4];     // gate-interleaved [bt*1024 + j*4 + g]
__device__ float    g_S[(size_t)BATCH * TT * UNITS];   // [bt*256 + j]

__device__ __forceinline__ float sigf(float x) {
    return __fdividef(1.0f, 1.0f + __expf(-x));
}
__device__ __forceinline__ float tanh_fast(float x) {
    return __fdividef(2.0f, 1.0f + __expf(-2.0f * x)) - 1.0f;
}

__device__ __forceinline__ uint32_t f2tf(float x) {
    uint32_t r;
    asm("cvt.rna.tf32.f32 %0, %1;" : "=r"(r) : "f"(x));
    return r;
}

__device__ __forceinline__ void mma_tf32(float* c, const uint32_t* a, const uint32_t* b) {
    asm volatile(
        "mma.sync.aligned.m16n8k8.row.col.f32.tf32.tf32.f32 "
        "{%0,%1,%2,%3}, {%4,%5,%6,%7}, {%8,%9}, {%0,%1,%2,%3};\n"
        : "+f"(c[0]), "+f"(c[1]), "+f"(c[2]), "+f"(c[3])
        : "r"(a[0]), "r"(a[1]), "r"(a[2]), "r"(a[3]), "r"(b[0]), "r"(b[1]));
}

__device__ __forceinline__ void mma_fp16(float* c, const uint32_t* a, const uint32_t* b) {
    asm volatile(
        "mma.sync.aligned.m16n8k16.row.col.f32.f16.f16.f32 "
        "{%0,%1,%2,%3}, {%4,%5,%6,%7}, {%8,%9}, {%0,%1,%2,%3};\n"
        : "+f"(c[0]), "+f"(c[1]), "+f"(c[2]), "+f"(c[3])
        : "r"(a[0]), "r"(a[1]), "r"(a[2]), "r"(a[3]), "r"(b[0]), "r"(b[1]));
}

// ---------------------------------------------------------------------------
// U[t][k][n] = sum_q Q[k, n*9+q] * B[t][q]
// ---------------------------------------------------------------------------
__global__ void build_U(const float* __restrict__ Q) {
    int t = blockIdx.x, i = blockIdx.y, j = threadIdx.x;
    __shared__ float Bq[QN];
    if (threadIdx.x < QN) {
        int q = threadIdx.x;
        float tt = (float)t / (float)(TT - 1);
        float v;
        if (q == 0) v = 1.0f;
        else {
            int h = (q + 1) >> 1;
            float w = 2.0f * PI_F * (float)h * tt;
            v = 1.41421356237309515f * ((q & 1) ? sinf(w) : cosf(w));
        }
        Bq[q] = v;
    }
    __syncthreads();
    const float* qrow = Q + (size_t)i * (UNITS * QN) + (size_t)j * QN;
    float acc = 0.0f;
#pragma unroll
    for (int q = 0; q < QN; q++) acc = fmaf(qrow[q], Bq[q], acc);
    g_U[((size_t)t * UNITS + i) * UNITS + j] = acc;
}

// ---------------------------------------------------------------------------
// x-part weights -> gate-interleaved columns: Whx[k][j*4+g]
// ---------------------------------------------------------------------------
__global__ void prep_Whx(const float* __restrict__ Wf, const float* __restrict__ Wi,
                         const float* __restrict__ Wc, const float* __restrict__ Wo) {
    int idx = blockIdx.x * blockDim.x + threadIdx.x;
    if (idx >= 256 * UNITS) return;
    int k = idx >> 8, j = idx & 255;
    int src = (k + 256) * UNITS + j;       // x-part = rows 256..511 of cat weight
    float4 v = make_float4(Wf[src], Wi[src], Wc[src], Wo[src]);
    *(float4*)(g_Whx + (size_t)k * G4 + (size_t)j * 4) = v;
}

// ---------------------------------------------------------------------------
// c-part weights -> fp16, m16n8k16 B-fragment order.
// uint2 idx = (kt*128 + nt)*32 + lane
//   n = nt*8 + (lane>>2); k0 = kt*16 + 2*(lane&3); j = n>>2; gate = n&3
//   .x = half2(W[k0][j],   W[k0+1][j])      (k 0..7 half of the tile)
//   .y = half2(W[k0+8][j], W[k0+9][j])      (k 8..15 half)
// ---------------------------------------------------------------------------
__global__ void prep_Wbh(const float* __restrict__ Wf, const float* __restrict__ Wi,
                         const float* __restrict__ Wc, const float* __restrict__ Wo) {
    int idx = blockIdx.x * blockDim.x + threadIdx.x;
    if (idx >= KT16 * 128 * 32) return;
    int lane = idx & 31;
    int nt = (idx >> 5) & 127;
    int kt = idx >> 12;
    int g = lane >> 2, tc = lane & 3;
    int n = nt * 8 + g;
    int j = n >> 2, gate = n & 3;
    int k0 = kt * 16 + 2 * tc;
    const float* W = (gate == 0) ? Wf : (gate == 1) ? Wi : (gate == 2) ? Wc : Wo;
    __half2 b0 = __floats2half2_rn(W[(size_t)k0 * UNITS + j],
                                   W[(size_t)(k0 + 1) * UNITS + j]);
    __half2 b1 = __floats2half2_rn(W[(size_t)(k0 + 8) * UNITS + j],
                                   W[(size_t)(k0 + 9) * UNITS + j]);
    uint2 o;
    o.x = *(uint32_t*)&b0;
    o.y = *(uint32_t*)&b1;
    g_Wbh[idx] = o;
}

// ---------------------------------------------------------------------------
// tf32 MMA GEMM: Xp = X(100352 x 256) @ Whx(256 x 1024); contiguous stores
// (measured 348us — unchanged)
// ---------------------------------------------------------------------------
__global__ __launch_bounds__(256) void xproj_mma(const float* __restrict__ A) {
    __shared__ uint32_t As[128][36];
    __shared__ uint32_t Bs[32][136];
    int tid = threadIdx.x;
    int bm = blockIdx.x, bn = blockIdx.y;
    int w = tid >> 5, lane = tid & 31;
    int wm = (w & 3) * 32, wn = (w >> 2) * 64;
    int g = lane >> 2, tc = lane & 3;

    const float* Ab = A + (size_t)bm * 128 * DIMF;
    const float* Bb = g_Whx + (size_t)bn * 128;

    int ar0 = tid >> 3, ac = (tid & 7) * 4;
    int br0 = tid >> 5, bc = (tid & 31) * 4;

    float c[2][8][4];
#pragma unroll
    for (int mi = 0; mi < 2; mi++)
#pragma unroll
        for (int ni = 0; ni < 8; ni++)
#pragma unroll
            for (int q = 0; q < 4; q++) c[mi][ni][q] = 0.0f;

    float4 ar[4], br[4];
#pragma unroll
    for (int i = 0; i < 4; i++) {
        ar[i] = *(const float4*)(Ab + (size_t)(ar0 + 32 * i) * DIMF + ac);
        br[i] = *(const float4*)(Bb + (size_t)(br0 + 8 * i) * G4 + bc);
    }

    for (int s = 0; s < 8; s++) {
        __syncthreads();
#pragma unroll
        for (int i = 0; i < 4; i++) {
            uint32_t* pa = &As[ar0 + 32 * i][ac];
            pa[0] = f2tf(ar[i].x); pa[1] = f2tf(ar[i].y);
            pa[2] = f2tf(ar[i].z); pa[3] = f2tf(ar[i].w);
            uint32_t* pb = &Bs[br0 + 8 * i][bc];
            pb[0] = f2tf(br[i].x); pb[1] = f2tf(br[i].y);
            pb[2] = f2tf(br[i].z); pb[3] = f2tf(br[i].w);
        }
        __syncthreads();
        if (s < 7) {
            int k0 = (s + 1) * 32;
#pragma unroll
            for (int i = 0; i < 4; i++) {
                ar[i] = *(const float4*)(Ab + (size_t)(ar0 + 32 * i) * DIMF + k0 + ac);
                br[i] = *(const float4*)(Bb + (size_t)(k0 + br0 + 8 * i) * G4 + bc);
            }
        }
#pragma unroll
        for (int kk = 0; kk < 4; kk++) {
            int k8 = kk * 8;
            uint32_t af[2][4];
#pragma unroll
            for (int mi = 0; mi < 2; mi++) {
                int r0 = wm + mi * 16 + g;
                af[mi][0] = As[r0][k8 + tc];
                af[mi][1] = As[r0 + 8][k8 + tc];
                af[mi][2] = As[r0][k8 + tc + 4];
                af[mi][3] = As[r0 + 8][k8 + tc + 4];
            }
            uint32_t bf[8][2];
#pragma unroll
            for (int ni = 0; ni < 8; ni++) {
                int nc = wn + ni * 8 + g;
                bf[ni][0] = Bs[k8 + tc][nc];
                bf[ni][1] = Bs[k8 + tc + 4][nc];
            }
#pragma unroll
            for (int mi = 0; mi < 2; mi++)
#pragma unroll
                for (int ni = 0; ni < 8; ni++)
                    mma_tf32(c[mi][ni], af[mi], bf[ni]);
        }
    }

#pragma unroll
    for (int mi = 0; mi < 2; mi++) {
#pragma unroll
        for (int ni = 0; ni < 8; ni++) {
            int row0 = bm * 128 + wm + mi * 16 + g;
            int n0 = bn * 128 + wn + ni * 8 + 2 * tc;
            *(float2*)(g_Xp + (size_t)row0 * G4 + n0) =
                make_float2(c[mi][ni][0], c[mi][ni][1]);
            *(float2*)(g_Xp + (size_t)(row0 + 8) * G4 + n0) =
                make_float2(c[mi][ni][2], c[mi][ni][3]);
        }
    }
}

// ---------------------------------------------------------------------------
// fp16 tensor-core recurrence. 128 blocks x 16 batch rows, 8 warps.
// Per t: G(16x1024) = c(fp16) @ Wbh(fp16), fp32 accum; gate smem staging;
// coalesced elementwise epilogue. Weight bytes halved vs tf32.
// ---------------------------------------------------------------------------
__global__ __launch_bounds__(256) void recur_mma() {
    extern __shared__ float sm[];
    float*  gs      = sm;                                 // [16][S_GS]
    float*  cs_full = sm + 16 * S_GS;                     // [16][S_CS]
    __half* cs_h    = (__half*)(cs_full + 16 * S_CS);     // [16][S_CH]

    int tid = threadIdx.x;
    int w = tid >> 5, lane = tid & 31;
    int g = lane >> 2, tc = lane & 3;
    int b0 = blockIdx.x * 16;

#pragma unroll
    for (int p = 0; p < 16; p++) {
        cs_full[p * S_CS + tid] = 0.0f;
        cs_h[p * S_CH + tid] = __float2half(0.0f);
    }
    __syncthreads();

    const uint2* __restrict__ Wbh = g_Wbh;
    const float4* __restrict__ Xp4 = (const float4*)g_Xp;

    for (int t = 0; t < TT; t++) {
        float acc[16][4];
#pragma unroll
        for (int ni = 0; ni < 16; ni++)
#pragma unroll
            for (int q = 0; q < 4; q++) acc[ni][q] = 0.0f;

#pragma unroll 2
        for (int kt = 0; kt < KT16; kt++) {
            int k2 = kt * 16;
            uint2 bf[16];
#pragma unroll
            for (int ni = 0; ni < 16; ni++)
                bf[ni] = Wbh[(size_t)((kt * 128) + w * 16 + ni) * 32 + lane];
            uint32_t ah[4];
            ah[0] = *(const uint32_t*)(cs_h + g * S_CH + k2 + 2 * tc);
            ah[1] = *(const uint32_t*)(cs_h + (g + 8) * S_CH + k2 + 2 * tc);
            ah[2] = *(const uint32_t*)(cs_h + g * S_CH + k2 + 2 * tc + 8);
            ah[3] = *(const uint32_t*)(cs_h + (g + 8) * S_CH + k2 + 2 * tc + 8);
#pragma unroll
            for (int ni = 0; ni < 16; ni++)
                mma_fp16(acc[ni], ah, (const uint32_t*)&bf[ni]);
        }

        // stage gate tile to smem (n ordering = j*4 + gate); C layout same as tf32
#pragma unroll
        for (int ni = 0; ni < 16; ni++) {
            int n0 = w * 128 + ni * 8 + 2 * tc;
            *(float2*)&gs[g * S_GS + n0]       = make_float2(acc[ni][0], acc[ni][1]);
            *(float2*)&gs[(g + 8) * S_GS + n0] = make_float2(acc[ni][2], acc[ni][3]);
        }
        __syncthreads();

#pragma unroll 4
        for (int p = 0; p < 16; p++) {
            float4 gv = *(const float4*)&gs[p * S_GS + 4 * tid];
            float4 xv = Xp4[((size_t)(b0 + p) * TT + t) * UNITS + tid];
            float f  = sigf(gv.x + xv.x);
            float i_ = sigf(gv.y + xv.y);
            float gg = sigf(gv.z + xv.z);
            float oo = tanh_fast(gv.w + xv.w);
            float cold = cs_full[p * S_CS + tid];
            float cnew = fmaf(f, cold, i_ * gg);
            cs_full[p * S_CS + tid] = cnew;
            cs_h[p * S_CH + tid] = __float2half_rn(cnew);
            g_S[((size_t)(b0 + p) * TT + t) * UNITS + tid] = oo * tanh_fast(cnew);
        }
        __syncthreads();
    }
}

// ---------------------------------------------------------------------------
// tf32 MMA: out[b,t,:] = tanh(S[b,t,:] @ U[t]); grid (16, 2, 49)
// ---------------------------------------------------------------------------
__global__ __launch_bounds__(256) void hproj_mma(float* __restrict__ out) {
    __shared__ uint32_t As[128][36];
    __shared__ uint32_t Bs[32][136];
    int tid = threadIdx.x;
    int bm = blockIdx.x, bn = blockIdx.y, t = blockIdx.z;
    int w = tid >> 5, lane = tid & 31;
    int wm = (w & 3) * 32, wn = (w >> 2) * 64;
    int g = lane >> 2, tc = lane & 3;

    const float* Ab = g_S + (size_t)bm * 128 * RS + (size_t)t * UNITS;
    const float* Bb = g_U + (size_t)t * UNITS * UNITS + (size_t)bn * 128;

    int ar0 = tid >> 3, ac = (tid & 7) * 4;
    int br0 = tid >> 5, bc = (tid & 31) * 4;

    float c[2][8][4];
#pragma unroll
    for (int mi = 0; mi < 2; mi++)
#pragma unroll
        for (int ni = 0; ni < 8; ni++)
#pragma unroll
            for (int q = 0; q < 4; q++) c[mi][ni][q] = 0.0f;

    float4 ar[4], br[4];
#pragma unroll
    for (int i = 0; i < 4; i++) {
        ar[i] = *(const float4*)(Ab + (size_t)(ar0 + 32 * i) * RS + ac);
        br[i] = *(const float4*)(Bb + (size_t)(br0 + 8 * i) * UNITS + bc);
    }

    for (int s = 0; s < 8; s++) {
        __syncthreads();
#pragma unroll
        for (int i = 0; i < 4; i++) {
            uint32_t* pa = &As[ar0 + 32 * i][ac];
            pa[0] = f2tf(ar[i].x); pa[1] = f2tf(ar[i].y);
            pa[2] = f2tf(ar[i].z); pa[3] = f2tf(ar[i].w);
            uint32_t* pb = &Bs[br0 + 8 * i][bc];
            pb[0] = f2tf(br[i].x); pb[1] = f2tf(br[i].y);
            pb[2] = f2tf(br[i].z); pb[3] = f2tf(br[i].w);
        }
        __syncthreads();
        if (s < 7) {
            int k0 = (s + 1) * 32;
#pragma unroll
            for (int i = 0; i < 4; i++) {
                ar[i] = *(const float4*)(Ab + (size_t)(ar0 + 32 * i) * RS + k0 + ac);
                br[i] = *(const float4*)(Bb + (size_t)(k0 + br0 + 8 * i) * UNITS + bc);
            }
        }
#pragma unroll
        for (int kk = 0; kk < 4; kk++) {
            int k8 = kk * 8;
            uint32_t af[2][4];
#pragma unroll
            for (int mi = 0; mi < 2; mi++) {
                int r0 = wm + mi * 16 + g;
                af[mi][0] = As[r0][k8 + tc];
                af[mi][1] = As[r0 + 8][k8 + tc];
                af[mi][2] = As[r0][k8 + tc + 4];
                af[mi][3] = As[r0 + 8][k8 + tc + 4];
            }
            uint32_t bf[8][2];
#pragma unroll
            for (int ni = 0; ni < 8; ni++) {
                int nc = wn + ni * 8 + g;
                bf[ni][0] = Bs[k8 + tc][nc];
                bf[ni][1] = Bs[k8 + tc + 4][nc];
            }
#pragma unroll
            for (int mi = 0; mi < 2; mi++)
#pragma unroll
                for (int ni = 0; ni < 8; ni++)
                    mma_tf32(c[mi][ni], af[mi], bf[ni]);
        }
    }

    float* Cb = out + (size_t)bm * 128 * RS + (size_t)t * UNITS + (size_t)bn * 128;
#pragma unroll
    for (int mi = 0; mi < 2; mi++) {
#pragma unroll
        for (int ni = 0; ni < 8; ni++) {
            int r0 = wm + mi * 16 + g;
            int col = wn + ni * 8 + 2 * tc;
            float2 v0 = make_float2(tanhf(c[mi][ni][0]), tanhf(c[mi][ni][1]));
            float2 v1 = make_float2(tanhf(c[mi][ni][2]), tanhf(c[mi][ni][3]));
            *(float2*)(Cb + (size_t)r0 * RS + col) = v0;
            *(float2*)(Cb + (size_t)(r0 + 8) * RS + col) = v1;
        }
    }
}

extern "C" void kernel_launch(void* const* d_in, const int* in_sizes, int n_in,
                              void* d_out, int out_size) {
    const float* x  = (const float*)d_in[0];
    const float* Wf = (const float*)d_in[1];
    const float* Wi = (const float*)d_in[2];
    const float* Wc = (const float*)d_in[3];
    const float* Wo = (const float*)d_in[4];
    const float* Q  = (const float*)d_in[5];
    float* out = (float*)d_out;

    cudaFuncSetAttribute(recur_mma, cudaFuncAttributeMaxDynamicSharedMemorySize, RECUR_SMEM);

    build_U<<<dim3(TT, UNITS), 256>>>(Q);
    prep_Whx<<<(256 * UNITS + 255) / 256, 256>>>(Wf, Wi, Wc, Wo);
    prep_Wbh<<<(KT16 * 128 * 32 + 255) / 256, 256>>>(Wf, Wi, Wc, Wo);
    xproj_mma<<<dim3(BATCH * TT / 128, G4 / 128), 256>>>(x);
    recur_mma<<<BATCH / 16, 256, RECUR_SMEM>>>();
    hproj_mma<<<dim3(BATCH / 128, UNITS / 128, TT), 256>>>(out);
}